// round 17
// baseline (speedup 1.0000x reference)
#include <cuda_runtime.h>
#include <cstdint>
#include <math.h>

// Problem constants
#define BATCH   32
#define SEQT    512
#define DIN     512
#define HID     512
#define LAYERS  2
#define G4      (4*HID)

// Persistent-kernel config
#define NCTA    128              // 64 CTAs per layer
#define CPL     64
#define THREADS 1024             // 32 warps = 2 j-quads x 16 k-groups
#define JPC     8

// SMEM float offsets
#define OFF_WX   0                       // [32 rows][512]
#define OFF_WH   16384
#define OFF_BUF  32768                   // 4 bufs x 4096 floats (packed pairs)
#define OFF_RED  OFF_BUF                 // 16384 floats, aliases all bufs post-compute
#define OFF_BIAS (OFF_BUF + 16384)
#define SMEM_FLOATS (OFF_BIAS + 32)
#define SMEM_BYTES  (SMEM_FLOATS * 4)    // ~196.7 KB

// ---------------- device scratch -------------------------------------------
__device__ float    g_xT[SEQT * DIN * BATCH];      // x transposed: [t][k][b]
__device__ float    g_h[LAYERS][2][HID * BATCH];   // ping-pong h per layer
__device__ unsigned g_arr[2];
__device__ unsigned g_rel[2];

// ---------------- transpose x + barrier reset (one launch) ------------------
__global__ void transpose_x_kernel(const float* __restrict__ x) {
    if (blockIdx.x == 0 && blockIdx.y == 0 &&
        threadIdx.x == 0 && threadIdx.y == 0) {
        g_arr[0] = 0u; g_arr[1] = 0u;
        g_rel[0] = 0u; g_rel[1] = 0u;
    }
    __shared__ float tile[32][33];
    int t  = blockIdx.x;
    int k0 = blockIdx.y * 32;
    int lx = threadIdx.x;
    for (int bb = threadIdx.y; bb < 32; bb += 8)
        tile[bb][lx] = x[((bb * SEQT + t) * DIN) + k0 + lx];
    __syncthreads();
    for (int kk = threadIdx.y; kk < 32; kk += 8)
        g_xT[(t * DIN + (k0 + kk)) * BATCH + lx] = tile[lx][kk];
}

// ---------------- helpers ----------------------------------------------------
// "memory" clobber is load-bearing (R8 bug: hoisted data loads past spin).
__device__ __forceinline__ unsigned ld_rel(const unsigned* p) {
    unsigned v;
    asm volatile("ld.global.cg.u32 %0, [%1];" : "=r"(v) : "l"(p) : "memory");
    return v;
}
__device__ __forceinline__ void spin_until(const unsigned* p, unsigned need) {
    while (ld_rel(p) < need) { __nanosleep(64); }
}

// per-layer 64-CTA barrier, cumulative generation
__device__ __forceinline__ void layer_barrier(int l, unsigned gen) {
    __threadfence();
    __syncthreads();
    if (threadIdx.x == 0) {
        unsigned a = atomicAdd(&g_arr[l], 1u);
        if (a + 1u == gen * (unsigned)CPL) {
            atomicExch(&g_rel[l], gen);
        } else {
            spin_until(&g_rel[l], gen);
        }
        __threadfence();
    }
    __syncthreads();
}

__device__ __forceinline__ float sigmoidf_(float v) {
    return 1.0f / (1.0f + expf(-v));
}

// packed f32x2 FMA: d = a*b + d
__device__ __forceinline__ void fma2(unsigned long long& d,
                                     unsigned long long a,
                                     unsigned long long b) {
    asm("fma.rn.f32x2 %0, %1, %2, %0;" : "+l"(d) : "l"(a), "l"(b));
}
__device__ __forceinline__ float2 u2f2(unsigned long long v) {
    float2 f;
    asm("mov.b64 {%0, %1}, %2;" : "=f"(f.x), "=f"(f.y) : "l"(v));
    return f;
}
struct ull2 { unsigned long long x, y; };

// One 16-k slice for warp (d = j-quad, q = k-group 0..15), round r (256 k).
__device__ __forceinline__ void compute_round(const float* smem, int r,
                                              int d, int q, int lane,
                                              unsigned long long* acc) {
    const int bs = q >> 3;                   // buf set: 0 = k[.,+128), 1 = +128
    const unsigned long long* in0p =
        (const unsigned long long*)(smem + OFF_BUF + (bs << 1) * 4096);
    const unsigned long long* in1p = in0p + 2048;   // next buf
    const int po  = (q & 7) << 3;            // pair offset 0,8,...,56
    const int kw0 = r * 256 + bs * 128 + (q & 7) * 16;
    #pragma unroll
    for (int i = 0; i < 4; ++i) {
        const int pi = po + 2 * i;
        unsigned long long p00 = in0p[(pi + 0) * 32 + lane];
        unsigned long long p01 = in0p[(pi + 1) * 32 + lane];
        unsigned long long p10 = in1p[(pi + 0) * 32 + lane];
        unsigned long long p11 = in1p[(pi + 1) * 32 + lane];
        const int kw = kw0 + 4 * i;
        #pragma unroll
        for (int j = 0; j < 4; ++j) {
            #pragma unroll
            for (int g = 0; g < 4; ++g) {
                const int row = ((d * 4 + j) * 4 + g) << 9;
                ull2 wx = *(const ull2*)&smem[OFF_WX + row + kw];
                ull2 wh = *(const ull2*)&smem[OFF_WH + row + kw];
                unsigned long long& a = acc[j * 4 + g];
                fma2(a, wx.x, p00);
                fma2(a, wx.y, p01);
                fma2(a, wh.x, p10);
                fma2(a, wh.y, p11);
            }
        }
    }
}

// ---------------- persistent LSTM kernel ------------------------------------
__global__ void __launch_bounds__(THREADS, 1)
lstm_persist(const float* __restrict__ h0,
             const float* __restrict__ c0,
             const float* __restrict__ Wx,   // [L][4H][D]
             const float* __restrict__ bx,
             const float* __restrict__ Wh,   // [L][4H][H]
             const float* __restrict__ bh,
             float* __restrict__ out,
             int out_size) {
    extern __shared__ float smem[];
    float* s_bias = smem + OFF_BIAS;

    const int cta   = blockIdx.x;
    const int l     = cta >> 6;              // layer 0/1
    const int jbase = (cta & 63) * JPC;
    const int tid   = threadIdx.x;
    const int w     = tid >> 5;              // 0..31
    const int lane  = tid & 31;              // batch index
    const int d_    = w >> 4;                // j-quad: j in [4d, 4d+4)
    const int q_    = w & 15;                // k-group 0..15 (16k per round)
    const bool owner = (w < 8);              // owner w finalizes jl = w
    const int  jl    = w & 7;
    const int  j     = jbase + jl;

    // ---- load this CTA's weight rows into SMEM (once) ----
    for (int i = tid * 4; i < 32 * 512; i += THREADS * 4) {
        int row  = i >> 9;                   // j_local*4 + gate
        int k    = i & 511;
        int grow = l * G4 + (row & 3) * HID + jbase + (row >> 2);
        *(float4*)&smem[OFF_WX + i] = *(const float4*)&Wx[(size_t)grow * DIN + k];
        *(float4*)&smem[OFF_WH + i] = *(const float4*)&Wh[(size_t)grow * HID + k];
    }
    if (tid < 32) {
        int grow = l * G4 + (tid & 3) * HID + jbase + (tid >> 2);
        s_bias[tid] = bx[grow] + bh[grow];   // s_bias[j*4 + g]
    }

    // ---- init state (owners hold c/h for their j) ----
    float c_reg  = c0[(lane * LAYERS + l) * HID + j];
    float h_last = h0[(lane * LAYERS + l) * HID + j];
    if (owner) {
        // both parities: g_h persists across graph replays
        __stcg(&g_h[l][0][j * BATCH + lane], h_last);
        __stcg(&g_h[l][1][j * BATCH + lane], h_last);
    }

    layer_barrier(l, 1u);

    // staging: half = tid>>9 stages bufs {2*half, 2*half+1} (k-half of event)
    const int half = tid >> 9;               // 0 or 1
    const int s_   = tid & 511;
    const int kp   = s_ >> 3;                // 0..63 (pair index)
    const int bg   = (s_ & 7) << 2;          // 0,4,...,28

    // ---- per-layer step loop (layer-1 trails via RAW wait; 2-step slack) ----
    for (int t = 0; t < SEQT; ++t) {
        if (l == 1) {
            spin_until(&g_rel[0], (unsigned)(t + 2));  // RAW: layer-0 step t done
            __syncthreads();   // no data load may precede the spin
        }
        const float* in0 = (l == 0) ? &g_xT[(size_t)t * DIN * BATCH]
                                    : &g_h[0][t & 1][0];
        const float* in1 = &g_h[l][(t + 1) & 1][0];

        unsigned long long acc[16];
        #pragma unroll
        for (int g = 0; g < 16; ++g) acc[g] = 0ull;

        float4 f[4];
        // ---- load + store event 0 (k[0,256)): this thread's 2 bufs ----
        {
            const int ks = half * 128 + 2 * kp;
            const float* s0 = in0 + ks * BATCH + bg;
            const float* s1 = in1 + ks * BATCH + bg;
            f[0] = __ldcg((const float4*)s0);
            f[1] = __ldcg((const float4*)(s0 + BATCH));
            f[2] = __ldcg((const float4*)s1);
            f[3] = __ldcg((const float4*)(s1 + BATCH));
        }
        {
            float* dst0 = smem + OFF_BUF + (half * 2 + 0) * 4096 + (kp * 32 + bg) * 2;
            float* dst1 = smem + OFF_BUF + (half * 2 + 1) * 4096 + (kp * 32 + bg) * 2;
            *(float4*)(dst0)     = make_float4(f[0].x, f[1].x, f[0].y, f[1].y);
            *(float4*)(dst0 + 4) = make_float4(f[0].z, f[1].z, f[0].w, f[1].w);
            *(float4*)(dst1)     = make_float4(f[2].x, f[3].x, f[2].y, f[3].y);
            *(float4*)(dst1 + 4) = make_float4(f[2].z, f[3].z, f[2].w, f[3].w);
        }
        __syncthreads();

        // ---- prefetch event 1 (k[256,512)) while computing round 0 ----
        {
            const int ks = 256 + half * 128 + 2 * kp;
            const float* s0 = in0 + ks * BATCH + bg;
            const float* s1 = in1 + ks * BATCH + bg;
            f[0] = __ldcg((const float4*)s0);
            f[1] = __ldcg((const float4*)(s0 + BATCH));
            f[2] = __ldcg((const float4*)s1);
            f[3] = __ldcg((const float4*)(s1 + BATCH));
        }

        compute_round(smem, 0, d_, q_, lane, acc);
        __syncthreads();

        {
            float* dst0 = smem + OFF_BUF + (half * 2 + 0) * 4096 + (kp * 32 + bg) * 2;
            float* dst1 = smem + OFF_BUF + (half * 2 + 1) * 4096 + (kp * 32 + bg) * 2;
            *(float4*)(dst0)     = make_float4(f[0].x, f[1].x, f[0].y, f[1].y);
            *(float4*)(dst0 + 4) = make_float4(f[0].z, f[1].z, f[0].w, f[1].w);
            *(float4*)(dst1)     = make_float4(f[2].x, f[3].x, f[2].y, f[3].y);
            *(float4*)(dst1 + 4) = make_float4(f[2].z, f[3].z, f[2].w, f[3].w);
        }
        __syncthreads();

        compute_round(smem, 1, d_, q_, lane, acc);
        __syncthreads();      // bufs free before red aliases onto them

        // ---- publish k-group partials: red[(row*16+q)*32+lane] ----
        #pragma unroll
        for (int idx = 0; idx < 16; ++idx) {
            const int jj = idx >> 2, g = idx & 3;
            const int row = (d_ * 4 + jj) * 4 + g;
            float2 v = u2f2(acc[idx]);
            smem[OFF_RED + (row * 16 + q_) * 32 + lane] = v.x + v.y;
        }
        // layer-0 WAR clearance (overlapped with publish; sync follows)
        if (l == 0 && tid == 0 && t >= 2) {
            spin_until(&g_rel[1], (unsigned)t);
        }
        __syncthreads();

        if (owner) {
            float pre[4];
            #pragma unroll
            for (int g = 0; g < 4; ++g) {
                const float* rp = &smem[OFF_RED + ((jl * 4 + g) * 16) * 32 + lane];
                float s0 = ((rp[0]   + rp[32])  + (rp[64]  + rp[96]))
                         + ((rp[128] + rp[160]) + (rp[192] + rp[224]));
                float s1 = ((rp[256] + rp[288]) + (rp[320] + rp[352]))
                         + ((rp[384] + rp[416]) + (rp[448] + rp[480]));
                pre[g] = (s0 + s1) + s_bias[(jl << 2) | g];
            }
            float ig = sigmoidf_(pre[0]);
            float fg = sigmoidf_(pre[1]);
            float gg = tanhf(pre[2]);
            float og = sigmoidf_(pre[3]);

            c_reg  = fg * c_reg + ig * gg;
            float hN = og * tanhf(c_reg);
            h_last = hN;

            __stcg(&g_h[l][t & 1][j * BATCH + lane], hN);
            if (l == 1)
                out[((size_t)lane * SEQT + t) * HID + j] = hN;
        }

        layer_barrier(l, (unsigned)(t + 2));
    }

    // ---- final h_n / c_n: [L][B][H] each, appended after output ----
    if (owner &&
        out_size >= BATCH * SEQT * HID + 2 * LAYERS * BATCH * HID) {
        float* hn = out + (size_t)BATCH * SEQT * HID;
        float* cn = hn + (size_t)LAYERS * BATCH * HID;
        hn[((size_t)l * BATCH + lane) * HID + j] = h_last;
        cn[((size_t)l * BATCH + lane) * HID + j] = c_reg;
    }
}

// ---------------- launch -----------------------------------------------------
extern "C" void kernel_launch(void* const* d_in, const int* in_sizes, int n_in,
                              void* d_out, int out_size) {
    const float* x  = (const float*)d_in[0];
    const float* h0 = (const float*)d_in[1];
    const float* c0 = (const float*)d_in[2];
    const float* Wx = (const float*)d_in[3];
    const float* bx = (const float*)d_in[4];
    const float* Wh = (const float*)d_in[5];
    const float* bh = (const float*)d_in[6];
    float* out = (float*)d_out;
    (void)in_sizes; (void)n_in;

    cudaFuncSetAttribute(lstm_persist,
                         cudaFuncAttributeMaxDynamicSharedMemorySize, SMEM_BYTES);

    dim3 tb(32, 8);
    dim3 tg(SEQT, DIN / 32);
    transpose_x_kernel<<<tg, tb>>>(x);   // also resets barrier state

    lstm_persist<<<NCTA, THREADS, SMEM_BYTES>>>(h0, c0, Wx, bx, Wh, bh, out, out_size);
}